// round 15
// baseline (speedup 1.0000x reference)
#include <cuda_runtime.h>
#include <cstdint>

#define T_STEPS 800
#define B_DIM   128
#define S_DIM   500
#define M_DIM   (T_STEPS * B_DIM)   /* 102400 */
#define BS      (B_DIM * S_DIM)     /* 64000  */

// Scratch: total[t,b,s] = input - err @ W^T
__device__ __align__(16) float g_total[(size_t)M_DIM * S_DIM];   // 204.8 MB

// ---------------------------------------------------------------------------
// f32x2 helpers: two independent IEEE-RN fp32 FMAs per op (bit-identical to
// two scalar FFMAs whether or not ptxas emits packed SASS).
// ---------------------------------------------------------------------------
__device__ __forceinline__ void ffma2(unsigned long long& c,
                                      unsigned long long a,
                                      unsigned long long b) {
    asm("fma.rn.f32x2 %0, %1, %2, %0;" : "+l"(c) : "l"(a), "l"(b));
}
__device__ __forceinline__ unsigned long long dup2(float x) {
    unsigned long long r;
    asm("mov.b64 %0, {%1, %2};" : "=l"(r) : "f"(x), "f"(x));
    return r;
}
__device__ __forceinline__ unsigned long long pack2(float x, float y) {
    unsigned long long r;
    asm("mov.b64 %0, {%1, %2};" : "=l"(r) : "f"(x), "f"(y));
    return r;
}
__device__ __forceinline__ float lo32(unsigned long long v) {
    float x, y;
    asm("mov.b64 {%0, %1}, %2;" : "=f"(x), "=f"(y) : "l"(v));
    return x;
}
__device__ __forceinline__ float hi32(unsigned long long v) {
    float x, y;
    asm("mov.b64 {%0, %1}, %2;" : "=f"(x), "=f"(y) : "l"(v));
    return y;
}

// ---------------------------------------------------------------------------
// GEMM: g_total[M,N] = input - err[M,K] * W[N,K]^T   (M=102400, N=K=500)
// 31 full smem k-tiles (k=0..495, no k-guards) + explicit 4-step tail
// (k=496..499). Per-element k order: 0..499 ascending fp32 RN FMA ->
// bit-identical to the proven rounds 1/8/12/13. At the fp32 pipe ceiling.
// ---------------------------------------------------------------------------
#define KT_MAIN 31

__global__ __launch_bounds__(256, 2) void gemm_f32x2(
    const float* __restrict__ input,
    const float* __restrict__ err,
    const float* __restrict__ W)
{
    const int K = S_DIM;
    const int N = S_DIM;
    const int BK = 16;

    __shared__ float As[2][16][128];
    __shared__ float Bs[2][16][128];

    const int tid = threadIdx.x;
    const int m0  = blockIdx.y * 128;
    const int n0  = blockIdx.x * 128;

    const int lrow = tid >> 2;          // 0..63
    const int lcol = (tid & 3) << 2;    // 0,4,8,12

    const float* aptr0 = err + (size_t)(m0 + lrow) * K + lcol;
    const float* aptr1 = aptr0 + (size_t)64 * K;
    const int nr0 = n0 + lrow;
    const int nr1 = n0 + lrow + 64;
    const float* bptr0 = W + (size_t)nr0 * K + lcol;
    const float* bptr1 = W + (size_t)nr1 * K + lcol;

    float4 pa0, pa1, pb0, pb1;
    const float4 f4z = make_float4(0.f, 0.f, 0.f, 0.f);

    auto LOADG = [&](int kt) {
        const int k0 = kt * BK;   // always in-bounds for kt <= 30
        pa0 = *(const float4*)(aptr0 + k0);
        pa1 = *(const float4*)(aptr1 + k0);
        pb0 = (nr0 < N) ? *(const float4*)(bptr0 + k0) : f4z;
        pb1 = (nr1 < N) ? *(const float4*)(bptr1 + k0) : f4z;
    };
    auto STOS = [&](int buf) {
        As[buf][lcol + 0][lrow]      = pa0.x;
        As[buf][lcol + 1][lrow]      = pa0.y;
        As[buf][lcol + 2][lrow]      = pa0.z;
        As[buf][lcol + 3][lrow]      = pa0.w;
        As[buf][lcol + 0][lrow + 64] = pa1.x;
        As[buf][lcol + 1][lrow + 64] = pa1.y;
        As[buf][lcol + 2][lrow + 64] = pa1.z;
        As[buf][lcol + 3][lrow + 64] = pa1.w;
        Bs[buf][lcol + 0][lrow]      = pb0.x;
        Bs[buf][lcol + 1][lrow]      = pb0.y;
        Bs[buf][lcol + 2][lrow]      = pb0.z;
        Bs[buf][lcol + 3][lrow]      = pb0.w;
        Bs[buf][lcol + 0][lrow + 64] = pb1.x;
        Bs[buf][lcol + 1][lrow + 64] = pb1.y;
        Bs[buf][lcol + 2][lrow + 64] = pb1.z;
        Bs[buf][lcol + 3][lrow + 64] = pb1.w;
    };

    const int tx = tid & 15;   // n-dir
    const int ty = tid >> 4;   // m-dir

    unsigned long long acc2[8][4];   // [m][n-pair]
#pragma unroll
    for (int i = 0; i < 8; ++i)
#pragma unroll
        for (int jp = 0; jp < 4; ++jp) acc2[i][jp] = 0ull;

    LOADG(0);
    STOS(0);
    __syncthreads();

    for (int kt = 0; kt < KT_MAIN; ++kt) {
        const int buf = kt & 1;
        if (kt + 1 < KT_MAIN) LOADG(kt + 1);

#pragma unroll
        for (int kk = 0; kk < BK; ++kk) {
            const float4 a0 = *(const float4*)&As[buf][kk][ty * 8];
            const float4 a1 = *(const float4*)&As[buf][kk][ty * 8 + 4];
            const float4 b0 = *(const float4*)&Bs[buf][kk][tx * 8];
            const float4 b1 = *(const float4*)&Bs[buf][kk][tx * 8 + 4];

            unsigned long long A[8];
            A[0] = dup2(a0.x); A[1] = dup2(a0.y);
            A[2] = dup2(a0.z); A[3] = dup2(a0.w);
            A[4] = dup2(a1.x); A[5] = dup2(a1.y);
            A[6] = dup2(a1.z); A[7] = dup2(a1.w);

            unsigned long long Bp[4];
            Bp[0] = pack2(b0.x, b0.y);
            Bp[1] = pack2(b0.z, b0.w);
            Bp[2] = pack2(b1.x, b1.y);
            Bp[3] = pack2(b1.z, b1.w);

#pragma unroll
            for (int i = 0; i < 8; ++i)
#pragma unroll
                for (int jp = 0; jp < 4; ++jp)
                    ffma2(acc2[i][jp], A[i], Bp[jp]);
        }

        if (kt + 1 < KT_MAIN) STOS(buf ^ 1);
        __syncthreads();
    }

    // ---- k tail: 496..499, ascending, cached global loads ----
#pragma unroll
    for (int kk2 = 0; kk2 < 4; ++kk2) {
        const int kx = 496 + kk2;
        unsigned long long A[8];
#pragma unroll
        for (int i = 0; i < 8; ++i)
            A[i] = dup2(__ldg(err + (size_t)(m0 + ty * 8 + i) * K + kx));
        float bv[8];
#pragma unroll
        for (int j = 0; j < 8; ++j) {
            const int n = n0 + tx * 8 + j;
            bv[j] = (n < N) ? __ldg(W + (size_t)n * K + kx) : 0.f;
        }
        unsigned long long Bp[4];
        Bp[0] = pack2(bv[0], bv[1]);
        Bp[1] = pack2(bv[2], bv[3]);
        Bp[2] = pack2(bv[4], bv[5]);
        Bp[3] = pack2(bv[6], bv[7]);
#pragma unroll
        for (int i = 0; i < 8; ++i)
#pragma unroll
            for (int jp = 0; jp < 4; ++jp)
                ffma2(acc2[i][jp], A[i], Bp[jp]);
    }

    // Epilogue: g_total = input - acc  (round-1 arithmetic order)
#pragma unroll
    for (int i = 0; i < 8; ++i) {
        const int m = m0 + ty * 8 + i;
        const float* inrow = input + (size_t)m * N;
        float* orow = g_total + (size_t)m * N;
#pragma unroll
        for (int jv = 0; jv < 2; ++jv) {
            const int n = n0 + tx * 8 + jv * 4;
            const float c0 = lo32(acc2[i][jv * 2 + 0]);
            const float c1 = hi32(acc2[i][jv * 2 + 0]);
            const float c2 = lo32(acc2[i][jv * 2 + 1]);
            const float c3 = hi32(acc2[i][jv * 2 + 1]);
            if (n + 4 <= N) {
                float4 iv = *(const float4*)(inrow + n);
                float4 ov;
                ov.x = iv.x - c0;
                ov.y = iv.y - c1;
                ov.z = iv.z - c2;
                ov.w = iv.w - c3;
                *(float4*)(orow + n) = ov;
            } else {
                const float cc[4] = {c0, c1, c2, c3};
#pragma unroll
                for (int jj = 0; jj < 4; ++jj)
                    if (n + jj < N)
                        orow[n + jj] = inrow[n + jj] - cc[jj];
            }
        }
    }
}

// ---------------------------------------------------------------------------
// Scan: 2 lanes/thread (float2), 128-thread blocks -> 250 CTAs (round-13
// measured optimum), with the load-batch window widened 16 -> 32 timesteps
// for more memory-level parallelism. Per-lane arithmetic byte-identical to
// the proven round-1 scan.
// ---------------------------------------------------------------------------
__global__ __launch_bounds__(128) void scan2_kernel(
    float* __restrict__ spks, float* __restrict__ traces)
{
    const int i = blockIdx.x * 128 + threadIdx.x;   // float2 index
    if (i >= BS / 2) return;

    const float ALPHA  = (float)(1.0 - 0.25 / 10.0);
    const float BETA   = (float)(1.0 - 0.25 / 20.0);
    const float KAPPA  = (float)(1.0 - 0.25 / 30.0);
    const float THRESH = 0.4f;

    float syn0 = 0.f, mem0 = 0.f, tr0 = 0.f;
    float syn1 = 0.f, mem1 = 0.f, tr1 = 0.f;

    const float2* p  = (const float2*)g_total + i;
    float2* ps = (float2*)spks + i;
    float2* pt = (float2*)traces + i;

    for (int t0 = 0; t0 < T_STEPS; t0 += 32) {
        float2 tot[32];
#pragma unroll
        for (int j = 0; j < 32; ++j)
            tot[j] = __ldcs(p + (size_t)(t0 + j) * (BS / 2));
#pragma unroll
        for (int j = 0; j < 32; ++j) {
            const float reset0 = (mem0 - THRESH) > 0.f ? 1.f : 0.f;
            syn0 = ALPHA * syn0 + tot[j].x;
            mem0 = (BETA * mem0 + syn0) * (1.f - reset0);
            const float spk0 = (mem0 - THRESH) > 0.f ? 1.f : 0.f;
            tr0 = KAPPA * tr0 + spk0;

            const float reset1 = (mem1 - THRESH) > 0.f ? 1.f : 0.f;
            syn1 = ALPHA * syn1 + tot[j].y;
            mem1 = (BETA * mem1 + syn1) * (1.f - reset1);
            const float spk1 = (mem1 - THRESH) > 0.f ? 1.f : 0.f;
            tr1 = KAPPA * tr1 + spk1;

            float2 s2; s2.x = spk0; s2.y = spk1;
            float2 t2; t2.x = tr0;  t2.y = tr1;
            __stcs(ps + (size_t)(t0 + j) * (BS / 2), s2);
            __stcs(pt + (size_t)(t0 + j) * (BS / 2), t2);
        }
    }
}

// ---------------------------------------------------------------------------
extern "C" void kernel_launch(void* const* d_in, const int* in_sizes, int n_in,
                              void* d_out, int out_size)
{
    const float* input = (const float*)d_in[0];   // (T,B,S)
    const float* err   = (const float*)d_in[1];   // (T,B,S)
    const float* W     = (const float*)d_in[2];   // (S,S)
    float* out = (float*)d_out;                   // [spks | traces]

    dim3 grid((S_DIM + 127) / 128, M_DIM / 128);  // (4, 800)
    gemm_f32x2<<<grid, 256>>>(input, err, W);

    scan2_kernel<<<(BS / 2 + 127) / 128, 128>>>(out, out + (size_t)T_STEPS * BS);
}

// round 16
// speedup vs baseline: 1.5699x; 1.5699x over previous
#include <cuda_runtime.h>
#include <cstdint>

#define T_STEPS 800
#define B_DIM   128
#define S_DIM   500
#define M_DIM   (T_STEPS * B_DIM)   /* 102400 */
#define BS      (B_DIM * S_DIM)     /* 64000  */

// Scratch: total[t,b,s] = input - err @ W^T
__device__ __align__(16) float g_total[(size_t)M_DIM * S_DIM];   // 204.8 MB

// ---------------------------------------------------------------------------
// f32x2 helpers: two independent IEEE-RN fp32 FMAs per op (bit-identical to
// two scalar FFMAs whether or not ptxas emits packed SASS).
// ---------------------------------------------------------------------------
__device__ __forceinline__ void ffma2(unsigned long long& c,
                                      unsigned long long a,
                                      unsigned long long b) {
    asm("fma.rn.f32x2 %0, %1, %2, %0;" : "+l"(c) : "l"(a), "l"(b));
}
__device__ __forceinline__ unsigned long long dup2(float x) {
    unsigned long long r;
    asm("mov.b64 %0, {%1, %2};" : "=l"(r) : "f"(x), "f"(x));
    return r;
}
__device__ __forceinline__ unsigned long long pack2(float x, float y) {
    unsigned long long r;
    asm("mov.b64 %0, {%1, %2};" : "=l"(r) : "f"(x), "f"(y));
    return r;
}
__device__ __forceinline__ float lo32(unsigned long long v) {
    float x, y;
    asm("mov.b64 {%0, %1}, %2;" : "=f"(x), "=f"(y) : "l"(v));
    return x;
}
__device__ __forceinline__ float hi32(unsigned long long v) {
    float x, y;
    asm("mov.b64 {%0, %1}, %2;" : "=f"(x), "=f"(y) : "l"(v));
    return y;
}

// ---------------------------------------------------------------------------
// GEMM: g_total[M,N] = input - err[M,K] * W[N,K]^T   (M=102400, N=K=500)
// 31 full smem k-tiles (k=0..495, no k-guards) + explicit 4-step tail
// (k=496..499). Per-element k order: 0..499 ascending fp32 RN FMA ->
// bit-identical to the proven rounds 1/8/12/13. At the fp32 pipe ceiling.
// ---------------------------------------------------------------------------
#define KT_MAIN 31

__global__ __launch_bounds__(256, 2) void gemm_f32x2(
    const float* __restrict__ input,
    const float* __restrict__ err,
    const float* __restrict__ W)
{
    const int K = S_DIM;
    const int N = S_DIM;
    const int BK = 16;

    __shared__ float As[2][16][128];
    __shared__ float Bs[2][16][128];

    const int tid = threadIdx.x;
    const int m0  = blockIdx.y * 128;
    const int n0  = blockIdx.x * 128;

    const int lrow = tid >> 2;          // 0..63
    const int lcol = (tid & 3) << 2;    // 0,4,8,12

    const float* aptr0 = err + (size_t)(m0 + lrow) * K + lcol;
    const float* aptr1 = aptr0 + (size_t)64 * K;
    const int nr0 = n0 + lrow;
    const int nr1 = n0 + lrow + 64;
    const float* bptr0 = W + (size_t)nr0 * K + lcol;
    const float* bptr1 = W + (size_t)nr1 * K + lcol;

    float4 pa0, pa1, pb0, pb1;
    const float4 f4z = make_float4(0.f, 0.f, 0.f, 0.f);

    auto LOADG = [&](int kt) {
        const int k0 = kt * BK;   // always in-bounds for kt <= 30
        pa0 = *(const float4*)(aptr0 + k0);
        pa1 = *(const float4*)(aptr1 + k0);
        pb0 = (nr0 < N) ? *(const float4*)(bptr0 + k0) : f4z;
        pb1 = (nr1 < N) ? *(const float4*)(bptr1 + k0) : f4z;
    };
    auto STOS = [&](int buf) {
        As[buf][lcol + 0][lrow]      = pa0.x;
        As[buf][lcol + 1][lrow]      = pa0.y;
        As[buf][lcol + 2][lrow]      = pa0.z;
        As[buf][lcol + 3][lrow]      = pa0.w;
        As[buf][lcol + 0][lrow + 64] = pa1.x;
        As[buf][lcol + 1][lrow + 64] = pa1.y;
        As[buf][lcol + 2][lrow + 64] = pa1.z;
        As[buf][lcol + 3][lrow + 64] = pa1.w;
        Bs[buf][lcol + 0][lrow]      = pb0.x;
        Bs[buf][lcol + 1][lrow]      = pb0.y;
        Bs[buf][lcol + 2][lrow]      = pb0.z;
        Bs[buf][lcol + 3][lrow]      = pb0.w;
        Bs[buf][lcol + 0][lrow + 64] = pb1.x;
        Bs[buf][lcol + 1][lrow + 64] = pb1.y;
        Bs[buf][lcol + 2][lrow + 64] = pb1.z;
        Bs[buf][lcol + 3][lrow + 64] = pb1.w;
    };

    const int tx = tid & 15;   // n-dir
    const int ty = tid >> 4;   // m-dir

    unsigned long long acc2[8][4];   // [m][n-pair]
#pragma unroll
    for (int i = 0; i < 8; ++i)
#pragma unroll
        for (int jp = 0; jp < 4; ++jp) acc2[i][jp] = 0ull;

    LOADG(0);
    STOS(0);
    __syncthreads();

    for (int kt = 0; kt < KT_MAIN; ++kt) {
        const int buf = kt & 1;
        if (kt + 1 < KT_MAIN) LOADG(kt + 1);

#pragma unroll
        for (int kk = 0; kk < BK; ++kk) {
            const float4 a0 = *(const float4*)&As[buf][kk][ty * 8];
            const float4 a1 = *(const float4*)&As[buf][kk][ty * 8 + 4];
            const float4 b0 = *(const float4*)&Bs[buf][kk][tx * 8];
            const float4 b1 = *(const float4*)&Bs[buf][kk][tx * 8 + 4];

            unsigned long long A[8];
            A[0] = dup2(a0.x); A[1] = dup2(a0.y);
            A[2] = dup2(a0.z); A[3] = dup2(a0.w);
            A[4] = dup2(a1.x); A[5] = dup2(a1.y);
            A[6] = dup2(a1.z); A[7] = dup2(a1.w);

            unsigned long long Bp[4];
            Bp[0] = pack2(b0.x, b0.y);
            Bp[1] = pack2(b0.z, b0.w);
            Bp[2] = pack2(b1.x, b1.y);
            Bp[3] = pack2(b1.z, b1.w);

#pragma unroll
            for (int i = 0; i < 8; ++i)
#pragma unroll
                for (int jp = 0; jp < 4; ++jp)
                    ffma2(acc2[i][jp], A[i], Bp[jp]);
        }

        if (kt + 1 < KT_MAIN) STOS(buf ^ 1);
        __syncthreads();
    }

    // ---- k tail: 496..499, ascending, cached global loads ----
#pragma unroll
    for (int kk2 = 0; kk2 < 4; ++kk2) {
        const int kx = 496 + kk2;
        unsigned long long A[8];
#pragma unroll
        for (int i = 0; i < 8; ++i)
            A[i] = dup2(__ldg(err + (size_t)(m0 + ty * 8 + i) * K + kx));
        float bv[8];
#pragma unroll
        for (int j = 0; j < 8; ++j) {
            const int n = n0 + tx * 8 + j;
            bv[j] = (n < N) ? __ldg(W + (size_t)n * K + kx) : 0.f;
        }
        unsigned long long Bp[4];
        Bp[0] = pack2(bv[0], bv[1]);
        Bp[1] = pack2(bv[2], bv[3]);
        Bp[2] = pack2(bv[4], bv[5]);
        Bp[3] = pack2(bv[6], bv[7]);
#pragma unroll
        for (int i = 0; i < 8; ++i)
#pragma unroll
            for (int jp = 0; jp < 4; ++jp)
                ffma2(acc2[i][jp], A[i], Bp[jp]);
    }

    // Epilogue: g_total = input - acc  (round-1 arithmetic order)
#pragma unroll
    for (int i = 0; i < 8; ++i) {
        const int m = m0 + ty * 8 + i;
        const float* inrow = input + (size_t)m * N;
        float* orow = g_total + (size_t)m * N;
#pragma unroll
        for (int jv = 0; jv < 2; ++jv) {
            const int n = n0 + tx * 8 + jv * 4;
            const float c0 = lo32(acc2[i][jv * 2 + 0]);
            const float c1 = hi32(acc2[i][jv * 2 + 0]);
            const float c2 = lo32(acc2[i][jv * 2 + 1]);
            const float c3 = hi32(acc2[i][jv * 2 + 1]);
            if (n + 4 <= N) {
                float4 iv = *(const float4*)(inrow + n);
                float4 ov;
                ov.x = iv.x - c0;
                ov.y = iv.y - c1;
                ov.z = iv.z - c2;
                ov.w = iv.w - c3;
                *(float4*)(orow + n) = ov;
            } else {
                const float cc[4] = {c0, c1, c2, c3};
#pragma unroll
                for (int jj = 0; jj < 4; ++jj)
                    if (n + jj < N)
                        orow[n + jj] = inrow[n + jj] - cc[jj];
            }
        }
    }
}

// ---------------------------------------------------------------------------
// Scan: 2 lanes/thread (float2), 128-thread blocks -> 250 CTAs (>= SM count),
// streaming cache hints, 16-step batches (measured optimum, round 13).
// Per-lane arithmetic identical to the proven round-1 scan.
// ---------------------------------------------------------------------------
__global__ __launch_bounds__(128) void scan2_kernel(
    float* __restrict__ spks, float* __restrict__ traces)
{
    const int i = blockIdx.x * 128 + threadIdx.x;   // float2 index
    if (i >= BS / 2) return;

    const float ALPHA  = (float)(1.0 - 0.25 / 10.0);
    const float BETA   = (float)(1.0 - 0.25 / 20.0);
    const float KAPPA  = (float)(1.0 - 0.25 / 30.0);
    const float THRESH = 0.4f;

    float syn0 = 0.f, mem0 = 0.f, tr0 = 0.f;
    float syn1 = 0.f, mem1 = 0.f, tr1 = 0.f;

    const float2* p  = (const float2*)g_total + i;
    float2* ps = (float2*)spks + i;
    float2* pt = (float2*)traces + i;

    for (int t0 = 0; t0 < T_STEPS; t0 += 16) {
        float2 tot[16];
#pragma unroll
        for (int j = 0; j < 16; ++j)
            tot[j] = __ldcs(p + (size_t)(t0 + j) * (BS / 2));
#pragma unroll
        for (int j = 0; j < 16; ++j) {
            const float reset0 = (mem0 - THRESH) > 0.f ? 1.f : 0.f;
            syn0 = ALPHA * syn0 + tot[j].x;
            mem0 = (BETA * mem0 + syn0) * (1.f - reset0);
            const float spk0 = (mem0 - THRESH) > 0.f ? 1.f : 0.f;
            tr0 = KAPPA * tr0 + spk0;

            const float reset1 = (mem1 - THRESH) > 0.f ? 1.f : 0.f;
            syn1 = ALPHA * syn1 + tot[j].y;
            mem1 = (BETA * mem1 + syn1) * (1.f - reset1);
            const float spk1 = (mem1 - THRESH) > 0.f ? 1.f : 0.f;
            tr1 = KAPPA * tr1 + spk1;

            float2 s2; s2.x = spk0; s2.y = spk1;
            float2 t2; t2.x = tr0;  t2.y = tr1;
            __stcs(ps + (size_t)(t0 + j) * (BS / 2), s2);
            __stcs(pt + (size_t)(t0 + j) * (BS / 2), t2);
        }
    }
}

// ---------------------------------------------------------------------------
extern "C" void kernel_launch(void* const* d_in, const int* in_sizes, int n_in,
                              void* d_out, int out_size)
{
    const float* input = (const float*)d_in[0];   // (T,B,S)
    const float* err   = (const float*)d_in[1];   // (T,B,S)
    const float* W     = (const float*)d_in[2];   // (S,S)
    float* out = (float*)d_out;                   // [spks | traces]

    dim3 grid((S_DIM + 127) / 128, M_DIM / 128);  // (4, 800)
    gemm_f32x2<<<grid, 256>>>(input, err, W);

    scan2_kernel<<<(BS / 2 + 127) / 128, 128>>>(out, out + (size_t)T_STEPS * BS);
}